// round 14
// baseline (speedup 1.0000x reference)
#include <cuda_runtime.h>
#include <math.h>
#include <stdint.h>

#define BB 16
#define NN 2048
#define KK 16
#define NPTS (BB*NN)   // 32768

// ---------------- scratch (device globals; no allocation allowed) ----------------
__device__ float gA[NPTS*128];
__device__ float gB[NPTS*128];
__device__ int   gIdx[NPTS*KK];
__device__ float gSq[NPTS];
__device__ float gPool[BB*1024];
__device__ float gY[BB*1024];

__device__ __forceinline__ void atomicMaxF(float* addr, float val){
    int old = __float_as_int(*addr);
    while (__int_as_float(old) < val) {
        int prev = atomicCAS((int*)addr, old, __float_as_int(val));
        if (prev == old) break;
        old = prev;
    }
}

// ---- packed f32x2 helpers (Blackwell): each lane is an exact IEEE fp32 FMA ----
__device__ __forceinline__ uint64_t pack2(float lo, float hi){
    uint64_t r;
    asm("mov.b64 %0, {%1,%2};" : "=l"(r) : "f"(lo), "f"(hi));
    return r;
}
__device__ __forceinline__ void unpack2(uint64_t v, float& lo, float& hi){
    asm("mov.b64 {%0,%1}, %2;" : "=f"(lo), "=f"(hi) : "l"(v));
}
#define FMA_F32X2(d, a, b) \
    asm("fma.rn.f32x2 %0, %1, %2, %0;" : "+l"(d) : "l"(a), "l"(b))

// ---------------- squared norms: one warp per row ----------------
__global__ void k_sq(const float* __restrict__ H, float* __restrict__ SQ, int C){
    int gt = blockIdx.x*blockDim.x + threadIdx.x;
    int row = gt >> 5;
    int lane = gt & 31;
    if (row >= NPTS) return;
    const float* p = H + (size_t)row*C;
    float s = 0.f;
    for (int c = lane; c < C; c += 32) { float v = p[c]; s = fmaf(v,v,s); }
    #pragma unroll
    for (int o=16;o>0;o>>=1) s += __shfl_down_sync(0xffffffffu, s, o);
    if (lane==0) SQ[row] = s;
}

// ---------------- specialized kNN for C=3: whole batch resident in smem ----------------
__global__ __launch_bounds__(256) void k_knn3(const float* __restrict__ X,
                                              const float* __restrict__ SQ,
                                              int* __restrict__ IDX){
    __shared__ float sP[NN*4];     // (x,y,z,sq) per point; reused as merge area
    const int t = threadIdx.x;
    const int row = t & 127, half = t >> 7;
    const int b = blockIdx.y;
    const int i0 = blockIdx.x * 128;
    const size_t baseRow = (size_t)b * NN;

    for (int e = t; e < NN; e += 256) {
        const float* p = X + (baseRow + e)*3;
        sP[e*4+0] = p[0];
        sP[e*4+1] = p[1];
        sP[e*4+2] = p[2];
        sP[e*4+3] = SQ[baseRow + e];
    }
    __syncthreads();

    const int iloc = i0 + row;
    const float xi = sP[iloc*4+0];
    const float yi = sP[iloc*4+1];
    const float zi = sP[iloc*4+2];
    const float sqa = sP[iloc*4+3];

    float td[16]; int ti[16];
    #pragma unroll
    for (int s = 0; s < 16; ++s) { td[s] = INFINITY; ti[s] = 0; }

    const int jb = half*1024;
    #pragma unroll 4
    for (int jj = 0; jj < 1024; ++jj) {
        const int j = jb + jj;
        float4 pj = *(const float4*)&sP[j*4];
        float dot = 0.f;
        dot = fmaf(xi, pj.x, dot);
        dot = fmaf(yi, pj.y, dot);
        dot = fmaf(zi, pj.z, dot);
        float d = sqa + pj.w - 2.f*dot;
        if (d < td[15]) {
            #pragma unroll
            for (int s = 15; s >= 1; --s) {
                bool cp = td[s-1] > d;
                bool cs = td[s]   > d;
                td[s] = cp ? td[s-1] : (cs ? d : td[s]);
                ti[s] = cp ? ti[s-1] : (cs ? j : ti[s]);
            }
            bool c0k = td[0] > d;
            td[0] = c0k ? d : td[0];
            ti[0] = c0k ? j : ti[0];
        }
    }
    __syncthreads();   // all reads of sP done before reuse as merge area

    {
        float* mrow = sP + row*64 + half*32;
        int*   mrowi = (int*)mrow + 16;
        #pragma unroll
        for (int s = 0; s < 16; ++s) { mrow[s] = td[s]; mrowi[s] = ti[s]; }
    }
    __syncthreads();
    if (t < 128) {
        const float* dAl = sP + t*64;
        const int*   iAl = (const int*)dAl + 16;
        const float* dBl = dAl + 32;
        const int*   iBl = iAl + 32;
        int pa = 0, pb = 0;
        int* o = IDX + (baseRow + i0 + t)*KK;
        #pragma unroll
        for (int s = 0; s < 16; ++s) {
            float da = dAl[pa], db = dBl[pb];
            int   ia = iAl[pa], ib = iBl[pb];
            bool takeA = (da < db) || (da == db && ia < ib);
            o[s] = takeA ? ia : ib;
            pa += takeA ? 1 : 0;
            pb += takeA ? 0 : 1;
        }
    }
}

// ---------------- kNN: tiled distance, f32x2 mainloop, register top-16 ----------------
// grid (N/128, B), 256 threads, 2 CTAs/SM. 128i x 64j tiles.
// C<=64: A resident (stride 132), full sD [128][68].
// C=128: A resident at stride 128 (fill ONCE), sD halved to [64][68] with
//        two row-passes per j-tile (rows split; each row still scans j ascending).
// Rows paired into f32x2 lanes — each lane is an exact fp32 FMA chain,
// c-sequential: bit-identical to the scalar version.
template<int C>
__global__ __launch_bounds__(256,2) void k_knn(const float* __restrict__ H,
                                               const float* __restrict__ SQ,
                                               int* __restrict__ IDX){
    constexpr int CHUNK = (C < 32) ? C : 32;
    constexpr int NC = C / CHUNK;
    constexpr bool ACH = (C > 64);
    constexpr int JT = 64;
    constexpr int AST = ACH ? 128 : 132;          // A stride
    constexpr int SA_FLOATS = C*AST;
    constexpr int SD_ROWS = ACH ? 64 : 128;

    extern __shared__ float sm[];
    float* sA   = sm;                    // [C][AST] resident
    float* sB   = sA + SA_FLOATS;        // [2][CHUNK][68]
    float* sD   = sB + 2*CHUNK*68;       // [SD_ROWS][68]
    float* sSqB = sD + SD_ROWS*68;       // [64]

    const int t  = threadIdx.x;
    const int tx = t & 15, ty = t >> 4;
    const int row = t & 127, half = t >> 7;
    const int b  = blockIdx.y;
    const int i0 = blockIdx.x * 128;
    const size_t baseRow = (size_t)b * NN;

    // resident A fill (once)
    #pragma unroll
    for (int q = 0; q < (128*(C/4))/256; ++q) {
        int i = t & 127;
        int c4 = (t >> 7) + q*2;
        float4 v = *(const float4*)&H[(baseRow + i0 + i)*(size_t)C + c4*4];
        sA[(c4*4+0)*AST + i] = v.x;
        sA[(c4*4+1)*AST + i] = v.y;
        sA[(c4*4+2)*AST + i] = v.z;
        sA[(c4*4+3)*AST + i] = v.w;
    }

    float td[16]; int ti[16];
    #pragma unroll
    for (int s = 0; s < 16; ++s) { td[s] = INFINITY; ti[s] = 0; }
    const float sqa = SQ[baseRow + i0 + row];

    for (int jt = 0; jt < NN/JT; ++jt) {
        __syncthreads();                 // prev scan done; buffers reusable
        const int j0 = jt*JT;
        if (t < JT) sSqB[t] = SQ[baseRow + j0 + t];

        // fill B chunk 0 into buffer 0
        #pragma unroll
        for (int q = 0; q < (JT*(CHUNK/4))/256; ++q) {
            int j = t & 63;
            int c4 = (t >> 6) + q*4;
            float4 v = *(const float4*)&H[(baseRow + j0 + j)*(size_t)C + c4*4];
            sB[(c4*4+0)*68 + j] = v.x;
            sB[(c4*4+1)*68 + j] = v.y;
            sB[(c4*4+2)*68 + j] = v.z;
            sB[(c4*4+3)*68 + j] = v.w;
        }

        uint64_t acc2[4][4];             // rowpair rp (rows ty*8+2rp, +1), col rj
        #pragma unroll
        for (int a=0;a<4;a++)
            #pragma unroll
            for (int c=0;c<4;c++) acc2[a][c]=0ull;

        float4 preB[2];
        for (int ch = 0; ch < NC; ++ch) {
            __syncthreads();
            if (NC > 1 && ch + 1 < NC) {
                const int c0n = (ch+1)*CHUNK;
                #pragma unroll
                for (int q = 0; q < 2; ++q) {
                    int j = t & 63;
                    int c4 = (t >> 6) + q*4;
                    preB[q] = *(const float4*)&H[(baseRow + j0 + j)*(size_t)C + c0n + c4*4];
                }
            }
            const float* aBase = sA + ch*CHUNK*AST + ty*8;
            const float* bBase = sB + (ch & 1)*(CHUNK*68) + tx*4;
            #pragma unroll
            for (int cc = 0; cc < CHUNK; ++cc) {
                ulonglong2 apA = *(const ulonglong2*)(aBase + cc*AST);
                ulonglong2 apB = *(const ulonglong2*)(aBase + cc*AST + 4);
                float4 b0 = *(const float4*)(bBase + cc*68);
                uint64_t bd0 = pack2(b0.x, b0.x);
                uint64_t bd1 = pack2(b0.y, b0.y);
                uint64_t bd2 = pack2(b0.z, b0.z);
                uint64_t bd3 = pack2(b0.w, b0.w);
                uint64_t ap[4] = {apA.x, apA.y, apB.x, apB.y};
                #pragma unroll
                for (int rp=0;rp<4;rp++){
                    FMA_F32X2(acc2[rp][0], ap[rp], bd0);
                    FMA_F32X2(acc2[rp][1], ap[rp], bd1);
                    FMA_F32X2(acc2[rp][2], ap[rp], bd2);
                    FMA_F32X2(acc2[rp][3], ap[rp], bd3);
                }
            }
            if (NC > 1 && ch + 1 < NC) {
                float* dB = sB + ((ch+1) & 1)*(CHUNK*68);
                #pragma unroll
                for (int q = 0; q < 2; ++q) {
                    int j = t & 63;
                    int c4 = (t >> 6) + q*4;
                    dB[(c4*4+0)*68 + j] = preB[q].x;
                    dB[(c4*4+1)*68 + j] = preB[q].y;
                    dB[(c4*4+2)*68 + j] = preB[q].z;
                    dB[(c4*4+3)*68 + j] = preB[q].w;
                }
            }
        }

        if (!ACH) {
            // write full dot tile, single scan pass
            #pragma unroll
            for (int rp=0;rp<4;rp++){
                float lo0,hi0,lo1,hi1,lo2,hi2,lo3,hi3;
                unpack2(acc2[rp][0], lo0, hi0);
                unpack2(acc2[rp][1], lo1, hi1);
                unpack2(acc2[rp][2], lo2, hi2);
                unpack2(acc2[rp][3], lo3, hi3);
                *(float4*)(sD + (ty*8+rp*2  )*68 + tx*4) = make_float4(lo0,lo1,lo2,lo3);
                *(float4*)(sD + (ty*8+rp*2+1)*68 + tx*4) = make_float4(hi0,hi1,hi2,hi3);
            }
            __syncthreads();
            const float* drow = sD + row*68 + half*32;
            const float* sqb  = sSqB + half*32;
            const int jb = j0 + half*32;
            #pragma unroll
            for (int g = 0; g < 8; ++g) {
                float4 v = *(const float4*)(drow + g*4);
                float dd[4] = {v.x, v.y, v.z, v.w};
                #pragma unroll
                for (int u = 0; u < 4; ++u) {
                    float d = sqa + sqb[g*4+u] - 2.f*dd[u];
                    if (d < td[15]) {
                        int jidx = jb + g*4 + u;
                        #pragma unroll
                        for (int s = 15; s >= 1; --s) {
                            bool cp = td[s-1] > d;
                            bool cs = td[s]   > d;
                            td[s] = cp ? td[s-1] : (cs ? d    : td[s]);
                            ti[s] = cp ? ti[s-1] : (cs ? jidx : ti[s]);
                        }
                        bool c0k = td[0] > d;
                        td[0] = c0k ? d    : td[0];
                        ti[0] = c0k ? jidx : ti[0];
                    }
                }
            }
        } else {
            // half-sized sD: two row-passes (rows split; j order per row unchanged)
            #pragma unroll
            for (int p = 0; p < 2; ++p) {
                if ((ty >> 3) == p) {
                    const int lr = ty*8 - p*64;
                    #pragma unroll
                    for (int rp=0;rp<4;rp++){
                        float lo0,hi0,lo1,hi1,lo2,hi2,lo3,hi3;
                        unpack2(acc2[rp][0], lo0, hi0);
                        unpack2(acc2[rp][1], lo1, hi1);
                        unpack2(acc2[rp][2], lo2, hi2);
                        unpack2(acc2[rp][3], lo3, hi3);
                        *(float4*)(sD + (lr+rp*2  )*68 + tx*4) = make_float4(lo0,lo1,lo2,lo3);
                        *(float4*)(sD + (lr+rp*2+1)*68 + tx*4) = make_float4(hi0,hi1,hi2,hi3);
                    }
                }
                __syncthreads();
                if ((row >> 6) == p) {
                    const float* drow = sD + (row & 63)*68 + half*32;
                    const float* sqb  = sSqB + half*32;
                    const int jb = j0 + half*32;
                    #pragma unroll
                    for (int g = 0; g < 8; ++g) {
                        float4 v = *(const float4*)(drow + g*4);
                        float dd[4] = {v.x, v.y, v.z, v.w};
                        #pragma unroll
                        for (int u = 0; u < 4; ++u) {
                            float d = sqa + sqb[g*4+u] - 2.f*dd[u];
                            if (d < td[15]) {
                                int jidx = jb + g*4 + u;
                                #pragma unroll
                                for (int s = 15; s >= 1; --s) {
                                    bool cp = td[s-1] > d;
                                    bool cs = td[s]   > d;
                                    td[s] = cp ? td[s-1] : (cs ? d    : td[s]);
                                    ti[s] = cp ? ti[s-1] : (cs ? jidx : ti[s]);
                                }
                                bool c0k = td[0] > d;
                                td[0] = c0k ? d    : td[0];
                                ti[0] = c0k ? jidx : ti[0];
                            }
                        }
                    }
                }
                __syncthreads();
            }
        }
    }
    __syncthreads();
    // merge area: ACH aliases the (now dead) resident A; else reuse sD
    float* mArea = ACH ? sm : sD;
    {
        float* mrow = mArea + row*64 + half*32;
        int*   mrowi = (int*)mrow + 16;
        #pragma unroll
        for (int s = 0; s < 16; ++s) { mrow[s] = td[s]; mrowi[s] = ti[s]; }
    }
    __syncthreads();
    // exact merge (lower distance wins; on equal distance, lower index wins)
    if (t < 128) {
        const float* dAl = mArea + t*64;
        const int*   iAl = (const int*)dAl + 16;
        const float* dBl = dAl + 32;
        const int*   iBl = iAl + 32;
        int pa = 0, pb = 0;
        int* o = IDX + (baseRow + i0 + t)*KK;
        #pragma unroll
        for (int s = 0; s < 16; ++s) {
            float da = dAl[pa], db = dBl[pb];
            int   ia = iAl[pa], ib = iBl[pb];
            bool takeA = (da < db) || (da == db && ia < ib);
            o[s] = takeA ? ia : ib;
            pa += takeA ? 1 : 0;
            pb += takeA ? 0 : 1;
        }
    }
}

// ---------------- cov features: [x, cov(knn xyz).flatten(9)] -> 12 ch ----------------
__global__ void k_cov(const float* __restrict__ X, const int* __restrict__ IDX,
                      float* __restrict__ OUT){
    int p = blockIdx.x*blockDim.x + threadIdx.x;
    if (p >= NPTS) return;
    int b = p >> 11;
    const int* id = IDX + (size_t)p*KK;
    float px[16], py[16], pz[16];
    float mx=0.f,my=0.f,mz=0.f;
    #pragma unroll
    for (int k=0;k<16;k++){
        int j = id[k];
        const float* q = X + ((size_t)(b<<11) + j)*3;
        px[k]=q[0]; py[k]=q[1]; pz[k]=q[2];
        mx+=px[k]; my+=py[k]; mz+=pz[k];
    }
    mx *= (1.f/16.f); my *= (1.f/16.f); mz *= (1.f/16.f);
    float c00=0,c01=0,c02=0,c11=0,c12=0,c22=0;
    #pragma unroll
    for (int k=0;k<16;k++){
        float cx=px[k]-mx, cy=py[k]-my, cz=pz[k]-mz;
        c00=fmaf(cx,cx,c00); c01=fmaf(cx,cy,c01); c02=fmaf(cx,cz,c02);
        c11=fmaf(cy,cy,c11); c12=fmaf(cy,cz,c12); c22=fmaf(cz,cz,c22);
    }
    const float* xi = X + (size_t)p*3;
    float* o = OUT + (size_t)p*12;
    o[0]=xi[0]; o[1]=xi[1]; o[2]=xi[2];
    o[3]=c00; o[4]=c01; o[5]=c02;
    o[6]=c01; o[7]=c11; o[8]=c12;
    o[9]=c02; o[10]=c12; o[11]=c22;
}

// ---------------- pointwise dense (kernel_size=1 conv), optional BN+ReLU ----------------
template<int CIN,int COUT,int RELU,int BN>
__global__ __launch_bounds__(256) void k_dense(const float* __restrict__ X,
        const float* __restrict__ W, const float* __restrict__ bias,
        const float* __restrict__ bg, const float* __restrict__ bb,
        const float* __restrict__ bm, const float* __restrict__ bv,
        float* __restrict__ OUT){
    extern __shared__ float sm[];
    float* Xs = sm;                  // [64][CIN] (CIN % 4 == 0)
    float* Ws = Xs + 64*CIN;         // [CIN][COUT]
    const int t = threadIdx.x;
    const size_t row0 = (size_t)blockIdx.x * 64;
    for (int e = t; e < (64*CIN)/4; e += 256)
        *(float4*)&Xs[e*4] = *(const float4*)&X[row0*CIN + e*4];
    for (int e = t; e < (CIN*COUT)/4; e += 256)
        *(float4*)&Ws[e*4] = *(const float4*)&W[e*4];
    __syncthreads();
    constexpr int CQ = COUT/4;
    for (int q = t; q < 32*CQ; q += 256) {
        int rp = q / CQ;
        int c4 = (q - rp*CQ)*4;
        float4 b4 = *(const float4*)(bias + c4);
        float a0[4] = {b4.x,b4.y,b4.z,b4.w};
        float a1[4] = {b4.x,b4.y,b4.z,b4.w};
        #pragma unroll 8
        for (int k=0;k<CIN;k++){
            float x0 = Xs[rp*CIN+k];
            float x1 = Xs[(rp+32)*CIN+k];
            float4 w = *(const float4*)(Ws + k*COUT + c4);
            a0[0]=fmaf(x0,w.x,a0[0]); a0[1]=fmaf(x0,w.y,a0[1]);
            a0[2]=fmaf(x0,w.z,a0[2]); a0[3]=fmaf(x0,w.w,a0[3]);
            a1[0]=fmaf(x1,w.x,a1[0]); a1[1]=fmaf(x1,w.y,a1[1]);
            a1[2]=fmaf(x1,w.z,a1[2]); a1[3]=fmaf(x1,w.w,a1[3]);
        }
        #pragma unroll
        for (int u=0;u<4;u++){
            float v0=a0[u], v1=a1[u];
            if (BN){
                int c = c4+u;
                float s   = bg[c]*rsqrtf(bv[c]+1e-3f);
                float off = bb[c] - bm[c]*s;
                v0 = fmaf(v0,s,off); v1 = fmaf(v1,s,off);
            }
            if (RELU){ v0=fmaxf(v0,0.f); v1=fmaxf(v1,0.f); }
            a0[u]=v0; a1[u]=v1;
        }
        *(float4*)(OUT + (row0+rp)*COUT + c4)    = make_float4(a0[0],a0[1],a0[2],a0[3]);
        *(float4*)(OUT + (row0+rp+32)*COUT + c4) = make_float4(a1[0],a1[1],a1[2],a1[3]);
    }
}

// ---------------- dense 128->128 (g2_lin): k-chunked, 3 CTAs/SM ----------------
__global__ __launch_bounds__(256,3) void k_dense128(const float* __restrict__ X,
        const float* __restrict__ W, const float* __restrict__ bias,
        float* __restrict__ OUT){
    extern __shared__ float sm[];
    float* Xs = sm;            // [64][128]
    float* Ws = Xs + 64*128;   // [2][32][128]
    const int t = threadIdx.x;
    const int c4 = (t & 31)*4;
    const int rp0 = t >> 5;    // 0..7
    const size_t row0 = (size_t)blockIdx.x * 64;

    #pragma unroll
    for (int q = 0; q < 8; ++q) {
        int e = t + q*256;
        *(float4*)&Xs[e*4] = *(const float4*)&X[row0*128 + e*4];
    }
    #pragma unroll
    for (int q = 0; q < 4; ++q) {
        int e = t + q*256;
        int k = e >> 5, cc4 = e & 31;
        *(float4*)&Ws[k*128 + cc4*4] = *(const float4*)&W[(size_t)k*128 + cc4*4];
    }

    float acc[8][4];
    {
        float4 b4 = *(const float4*)(bias + c4);
        #pragma unroll
        for (int m=0;m<8;m++){ acc[m][0]=b4.x; acc[m][1]=b4.y; acc[m][2]=b4.z; acc[m][3]=b4.w; }
    }

    float4 preW[4];
    for (int kc = 0; kc < 4; ++kc) {
        __syncthreads();
        if (kc + 1 < 4) {
            const int k0n = (kc+1)*32;
            #pragma unroll
            for (int q = 0; q < 4; ++q) {
                int e = t + q*256;
                int k = e >> 5, cc4 = e & 31;
                preW[q] = *(const float4*)&W[(size_t)(k0n + k)*128 + cc4*4];
            }
        }
        const float* wb = Ws + (kc & 1)*(32*128);
        #pragma unroll
        for (int kk = 0; kk < 32; ++kk) {
            float4 w = *(const float4*)(wb + kk*128 + c4);
            int k = kc*32 + kk;
            #pragma unroll
            for (int m = 0; m < 8; ++m) {
                int r = rp0 + ((m & 3) << 3) + ((m >> 2) << 5);
                float x = Xs[r*128 + k];
                acc[m][0]=fmaf(x,w.x,acc[m][0]); acc[m][1]=fmaf(x,w.y,acc[m][1]);
                acc[m][2]=fmaf(x,w.z,acc[m][2]); acc[m][3]=fmaf(x,w.w,acc[m][3]);
            }
        }
        if (kc + 1 < 4) {
            float* wdst = Ws + ((kc+1) & 1)*(32*128);
            #pragma unroll
            for (int q = 0; q < 4; ++q) {
                int e = t + q*256;
                int k = e >> 5, cc4 = e & 31;
                *(float4*)&wdst[k*128 + cc4*4] = preW[q];
            }
        }
    }
    #pragma unroll
    for (int m = 0; m < 8; ++m) {
        int r = rp0 + ((m & 3) << 3) + ((m >> 2) << 5);
        *(float4*)(OUT + (row0 + r)*128 + c4) =
            make_float4(acc[m][0],acc[m][1],acc[m][2],acc[m][3]);
    }
}

// ---------------- gather neighbors + max over k ----------------
template<int C>
__global__ void k_gmax(const float* __restrict__ H, const int* __restrict__ IDX,
                       float* __restrict__ OUT){
    constexpr int CQ = C/4;
    int e = blockIdx.x*blockDim.x + threadIdx.x;
    if (e >= NPTS*CQ) return;
    int p = e / CQ, c4 = (e - p*CQ)*4;
    int b = p >> 11;
    const int* id = IDX + (size_t)p*KK;
    float4 m = make_float4(-INFINITY,-INFINITY,-INFINITY,-INFINITY);
    #pragma unroll
    for (int k=0;k<16;k++){
        int j = id[k];
        float4 v = *(const float4*)(H + ((size_t)(b<<11)+j)*C + c4);
        m.x=fmaxf(m.x,v.x); m.y=fmaxf(m.y,v.y);
        m.z=fmaxf(m.z,v.z); m.w=fmaxf(m.w,v.w);
    }
    *(float4*)(OUT + (size_t)p*C + c4) = m;
}

// ---------------- 128->1024 GEMM fused with bias + global max over N ----------------
// f32x2 rowpair mainloop (lane0 = even row, lane1 = odd row); bit-identical.
__global__ __launch_bounds__(256,2) void k_gemm_pool(const float* __restrict__ X,
        const float* __restrict__ W, const float* __restrict__ bias,
        float* __restrict__ pool){
    extern __shared__ float sm[];
    float* XsT  = sm;              // [128 k][132 i]
    float* Ws   = XsT + 128*132;   // [128 k][68 c]
    float* sred = Ws  + 128*68;    // [64 c][17]
    const int t = threadIdx.x, tx = t & 15, ty = t >> 4;
    const int b = blockIdx.z;
    const size_t row0 = (size_t)b*NN + (size_t)blockIdx.y*128;
    const int c0 = blockIdx.x*64;

    #pragma unroll
    for (int q = 0; q < 16; ++q) {
        int i = t & 127;
        int k4 = (t >> 7) + q*2;
        float4 v = *(const float4*)&X[(row0 + i)*128 + k4*4];
        XsT[(k4*4+0)*132 + i] = v.x;
        XsT[(k4*4+1)*132 + i] = v.y;
        XsT[(k4*4+2)*132 + i] = v.z;
        XsT[(k4*4+3)*132 + i] = v.w;
    }
    #pragma unroll
    for (int q = 0; q < 8; ++q) {
        int c4 = t & 15;
        int k = (t >> 4) + q*16;
        *(float4*)&Ws[k*68 + c4*4] = *(const float4*)&W[(size_t)k*1024 + c0 + c4*4];
    }
    __syncthreads();

    uint64_t acc2[4][4];
    #pragma unroll
    for (int a=0;a<4;a++)
        #pragma unroll
        for (int c=0;c<4;c++) acc2[a][c]=0ull;

    const float* aBase = XsT + ty*8;
    const float* wBase = Ws  + tx*4;
    #pragma unroll 8
    for (int k=0;k<128;k++){
        ulonglong2 apA = *(const ulonglong2*)(aBase + k*132);
        ulonglong2 apB = *(const ulonglong2*)(aBase + k*132 + 4);
        float4 w0 = *(const float4*)(wBase + k*68);
        uint64_t wd0 = pack2(w0.x, w0.x);
        uint64_t wd1 = pack2(w0.y, w0.y);
        uint64_t wd2 = pack2(w0.z, w0.z);
        uint64_t wd3 = pack2(w0.w, w0.w);
        uint64_t ap[4] = {apA.x, apA.y, apB.x, apB.y};
        #pragma unroll
        for (int rp=0;rp<4;rp++){
            FMA_F32X2(acc2[rp][0], ap[rp], wd0);
            FMA_F32X2(acc2[rp][1], ap[rp], wd1);
            FMA_F32X2(acc2[rp][2], ap[rp], wd2);
            FMA_F32X2(acc2[rp][3], ap[rp], wd3);
        }
    }
    // rows = ty*8 + 2rp + lane; per-col max over this thread's 8 rows (order 0..7)
    #pragma unroll
    for (int rj=0;rj<4;rj++){
        float m = -INFINITY;
        #pragma unroll
        for (int rp=0;rp<4;rp++){
            float lo, hi;
            unpack2(acc2[rp][rj], lo, hi);
            m = fmaxf(m, lo);
            m = fmaxf(m, hi);
        }
        sred[(tx*4+rj)*17 + ty] = m;
    }
    __syncthreads();
    if (t < 64){
        float m = sred[t*17];
        #pragma unroll
        for (int q=1;q<16;q++) m = fmaxf(m, sred[t*17+q]);
        m += bias[c0 + t];
        atomicMaxF(&pool[b*1024 + c0 + t], m);
    }
}

__global__ void k_init(float* __restrict__ p, int n){
    int e = blockIdx.x*blockDim.x + threadIdx.x;
    if (e < n) p[e] = -INFINITY;
}

// ---------------- tiny FC layers over pooled [B, CIN] ----------------
template<int CIN,int COUT,int RELU>
__global__ __launch_bounds__(256) void k_fc(const float* __restrict__ IN,
        const float* __restrict__ W, const float* __restrict__ bias,
        float* __restrict__ OUT){
    __shared__ float Ps[CIN];
    const int t = threadIdx.x;
    const int b = blockIdx.y;
    const int c = blockIdx.x*256 + t;
    for (int e=t;e<CIN;e+=256) Ps[e]=IN[b*CIN+e];
    __syncthreads();
    float acc = bias[c];
    #pragma unroll 8
    for (int k=0;k<CIN;k++) acc = fmaf(Ps[k], W[(size_t)k*COUT + c], acc);
    if (RELU) acc = fmaxf(acc, 0.f);
    OUT[b*COUT + c] = acc;
}

// ---------------- host ----------------
static inline int knn_smem(int C){
    int ch = C < 32 ? C : 32;
    if (C > 64)
        return (C*128 + 2*ch*68 + 64*68 + 64)*4;   // merge aliases resident A
    return (C*132 + 2*ch*68 + 128*68 + 64)*4;
}
static inline int dense_smem(int cin, int cout){
    return (64*cin + cin*cout)*4;
}
#define GEMM_SMEM ((128*132 + 128*68 + 64*17)*4)
#define DENSE128_SMEM ((64*128 + 2*32*128)*4)

extern "C" void kernel_launch(void* const* d_in, const int* in_sizes, int n_in,
                              void* d_out, int out_size){
    const float* x    = (const float*)d_in[0];
    const float* c1w  = (const float*)d_in[1];
    const float* c1b  = (const float*)d_in[2];
    const float* c2w  = (const float*)d_in[3];
    const float* c2b  = (const float*)d_in[4];
    const float* c3w  = (const float*)d_in[5];
    const float* c3b  = (const float*)d_in[6];
    const float* g1lw = (const float*)d_in[7];
    const float* g1lb = (const float*)d_in[8];
    const float* g1cw = (const float*)d_in[9];
    const float* g1cb = (const float*)d_in[10];
    const float* g2lw = (const float*)d_in[11];
    const float* g2lb = (const float*)d_in[12];
    const float* g2cw = (const float*)d_in[13];
    const float* g2cb = (const float*)d_in[14];
    const float* c4w  = (const float*)d_in[15];
    const float* c4b  = (const float*)d_in[16];
    const float* c5w  = (const float*)d_in[17];
    const float* c5b  = (const float*)d_in[18];
    const float* bn1g = (const float*)d_in[19];
    const float* bn1b = (const float*)d_in[20];
    const float* bn1m = (const float*)d_in[21];
    const float* bn1v = (const float*)d_in[22];
    const float* bn2g = (const float*)d_in[23];
    const float* bn2b = (const float*)d_in[24];
    const float* bn2m = (const float*)d_in[25];
    const float* bn2v = (const float*)d_in[26];
    const float* bn3g = (const float*)d_in[27];
    const float* bn3b = (const float*)d_in[28];
    const float* bn3m = (const float*)d_in[29];
    const float* bn3v = (const float*)d_in[30];
    float* out = (float*)d_out;

    float *A,*B,*SQ,*POOL,*Y; int* ID;
    cudaGetSymbolAddress((void**)&A, gA);
    cudaGetSymbolAddress((void**)&B, gB);
    cudaGetSymbolAddress((void**)&SQ, gSq);
    cudaGetSymbolAddress((void**)&POOL, gPool);
    cudaGetSymbolAddress((void**)&Y, gY);
    cudaGetSymbolAddress((void**)&ID, gIdx);

    cudaFuncSetAttribute(k_knn<64>,  cudaFuncAttributeMaxDynamicSharedMemorySize, knn_smem(64));
    cudaFuncSetAttribute(k_knn<128>, cudaFuncAttributeMaxDynamicSharedMemorySize, knn_smem(128));
    cudaFuncSetAttribute(k_gemm_pool, cudaFuncAttributeMaxDynamicSharedMemorySize, GEMM_SMEM);
    cudaFuncSetAttribute(k_dense128,  cudaFuncAttributeMaxDynamicSharedMemorySize, DENSE128_SMEM);
    cudaFuncSetAttribute((void*)k_dense<64,128,1,0>, cudaFuncAttributeMaxDynamicSharedMemorySize,
                         dense_smem(64,128));

    const dim3 knnGrid(NN/128, BB);   // 256 blocks

    // stage 0: knn on xyz (specialized, batch-resident) + covariance features
    k_sq<<<(NPTS*32)/256, 256>>>(x, SQ, 3);
    k_knn3<<<knnGrid, 256>>>(x, SQ, ID);
    k_cov<<<NPTS/256, 256>>>(x, ID, A);                       // A: [*,12]

    // MLP stack with BN+ReLU
    k_dense<12,12,1,1><<<NPTS/64, 256, dense_smem(12,12)>>>(A, c1w, c1b, bn1g,bn1b,bn1m,bn1v, B);
    k_dense<12,64,1,1><<<NPTS/64, 256, dense_smem(12,64)>>>(B, c2w, c2b, bn2g,bn2b,bn2m,bn2v, A);
    k_dense<64,64,1,1><<<NPTS/64, 256, dense_smem(64,64)>>>(A, c3w, c3b, bn3g,bn3b,bn3m,bn3v, B); // h64 in B

    // graph layer 1 (C=64 -> 128, relu)
    k_sq<<<(NPTS*32)/256, 256>>>(B, SQ, 64);
    k_knn<64><<<knnGrid, 256, knn_smem(64)>>>(B, SQ, ID);
    k_gmax<64><<<(NPTS*16)/256, 256>>>(B, ID, A);
    k_dense<64,64,0,0><<<NPTS/64, 256, dense_smem(64,64)>>>(A, g1lw, g1lb, 0,0,0,0, B);
    k_dense<64,128,1,0><<<NPTS/64, 256, dense_smem(64,128)>>>(B, g1cw, g1cb, 0,0,0,0, A); // h128 in A

    // graph layer 2 (C=128 -> 1024, no relu) fused with global max pool
    k_sq<<<(NPTS*32)/256, 256>>>(A, SQ, 128);
    k_knn<128><<<knnGrid, 256, knn_smem(128)>>>(A, SQ, ID);
    k_gmax<128><<<(NPTS*32)/256, 256>>>(A, ID, B);
    k_dense128<<<NPTS/64, 256, DENSE128_SMEM>>>(B, g2lw, g2lb, A);
    k_init<<<(BB*1024)/256, 256>>>(POOL, BB*1024);
    k_gemm_pool<<<dim3(1024/64, NN/128, BB), 256, GEMM_SMEM>>>(A, g2cw, g2cb, POOL);

    // head
    k_fc<1024,1024,1><<<dim3(1024/256, BB), 256>>>(POOL, c4w, c4b, Y);
    k_fc<1024,512,0><<<dim3(512/256, BB), 256>>>(Y, c5w, c5b, out);
}

// round 16
// speedup vs baseline: 1.0854x; 1.0854x over previous
#include <cuda_runtime.h>
#include <math.h>
#include <stdint.h>

#define BB 16
#define NN 2048
#define KK 16
#define NPTS (BB*NN)   // 32768

// ---------------- scratch (device globals; no allocation allowed) ----------------
__device__ float gA[NPTS*128];
__device__ float gB[NPTS*128];
__device__ int   gIdx[NPTS*KK];
__device__ float gSq[NPTS];
__device__ float gPool[BB*1024];
__device__ float gY[BB*1024];

__device__ __forceinline__ void atomicMaxF(float* addr, float val){
    int old = __float_as_int(*addr);
    while (__int_as_float(old) < val) {
        int prev = atomicCAS((int*)addr, old, __float_as_int(val));
        if (prev == old) break;
        old = prev;
    }
}

// ---- packed f32x2 helpers (Blackwell): each lane is an exact IEEE fp32 FMA ----
__device__ __forceinline__ uint64_t pack2(float lo, float hi){
    uint64_t r;
    asm("mov.b64 %0, {%1,%2};" : "=l"(r) : "f"(lo), "f"(hi));
    return r;
}
__device__ __forceinline__ void unpack2(uint64_t v, float& lo, float& hi){
    asm("mov.b64 {%0,%1}, %2;" : "=f"(lo), "=f"(hi) : "l"(v));
}
#define FMA_F32X2(d, a, b) \
    asm("fma.rn.f32x2 %0, %1, %2, %0;" : "+l"(d) : "l"(a), "l"(b))

// ---------------- squared norms: one warp per row ----------------
__global__ void k_sq(const float* __restrict__ H, float* __restrict__ SQ, int C){
    int gt = blockIdx.x*blockDim.x + threadIdx.x;
    int row = gt >> 5;
    int lane = gt & 31;
    if (row >= NPTS) return;
    const float* p = H + (size_t)row*C;
    float s = 0.f;
    for (int c = lane; c < C; c += 32) { float v = p[c]; s = fmaf(v,v,s); }
    #pragma unroll
    for (int o=16;o>0;o>>=1) s += __shfl_down_sync(0xffffffffu, s, o);
    if (lane==0) SQ[row] = s;
}

// ---------------- specialized kNN for C=3: whole batch resident in smem ----------------
__global__ __launch_bounds__(256) void k_knn3(const float* __restrict__ X,
                                              const float* __restrict__ SQ,
                                              int* __restrict__ IDX){
    __shared__ float sP[NN*4];     // (x,y,z,sq) per point; reused as merge area
    const int t = threadIdx.x;
    const int row = t & 127, half = t >> 7;
    const int b = blockIdx.y;
    const int i0 = blockIdx.x * 128;
    const size_t baseRow = (size_t)b * NN;

    for (int e = t; e < NN; e += 256) {
        const float* p = X + (baseRow + e)*3;
        sP[e*4+0] = p[0];
        sP[e*4+1] = p[1];
        sP[e*4+2] = p[2];
        sP[e*4+3] = SQ[baseRow + e];
    }
    __syncthreads();

    const int iloc = i0 + row;
    const float xi = sP[iloc*4+0];
    const float yi = sP[iloc*4+1];
    const float zi = sP[iloc*4+2];
    const float sqa = sP[iloc*4+3];

    float td[16]; int ti[16];
    #pragma unroll
    for (int s = 0; s < 16; ++s) { td[s] = INFINITY; ti[s] = 0; }

    const int jb = half*1024;
    #pragma unroll 4
    for (int jj = 0; jj < 1024; ++jj) {
        const int j = jb + jj;
        float4 pj = *(const float4*)&sP[j*4];
        float dot = 0.f;
        dot = fmaf(xi, pj.x, dot);
        dot = fmaf(yi, pj.y, dot);
        dot = fmaf(zi, pj.z, dot);
        float d = sqa + pj.w - 2.f*dot;
        if (d < td[15]) {
            #pragma unroll
            for (int s = 15; s >= 1; --s) {
                bool cp = td[s-1] > d;
                bool cs = td[s]   > d;
                td[s] = cp ? td[s-1] : (cs ? d : td[s]);
                ti[s] = cp ? ti[s-1] : (cs ? j : ti[s]);
            }
            bool c0k = td[0] > d;
            td[0] = c0k ? d : td[0];
            ti[0] = c0k ? j : ti[0];
        }
    }
    __syncthreads();   // all reads of sP done before reuse as merge area

    {
        float* mrow = sP + row*64 + half*32;
        int*   mrowi = (int*)mrow + 16;
        #pragma unroll
        for (int s = 0; s < 16; ++s) { mrow[s] = td[s]; mrowi[s] = ti[s]; }
    }
    __syncthreads();
    if (t < 128) {
        const float* dAl = sP + t*64;
        const int*   iAl = (const int*)dAl + 16;
        const float* dBl = dAl + 32;
        const int*   iBl = iAl + 32;
        int pa = 0, pb = 0;
        int* o = IDX + (baseRow + i0 + t)*KK;
        #pragma unroll
        for (int s = 0; s < 16; ++s) {
            float da = dAl[pa], db = dBl[pb];
            int   ia = iAl[pa], ib = iBl[pb];
            bool takeA = (da < db) || (da == db && ia < ib);
            o[s] = takeA ? ia : ib;
            pa += takeA ? 1 : 0;
            pb += takeA ? 0 : 1;
        }
    }
}

// ---------------- kNN: tiled distance, f32x2 mainloop, register top-16 ----------------
// grid (N/128, B), 256 threads, 2 CTAs/SM. 128i x 64j tiles.
// Rows paired into f32x2 lanes (lane0=even row, lane1=odd row) — each lane is
// an exact fp32 FMA chain, c-sequential: bit-identical to the scalar version.
template<int C>
__global__ __launch_bounds__(256,2) void k_knn(const float* __restrict__ H,
                                               const float* __restrict__ SQ,
                                               int* __restrict__ IDX){
    constexpr int CHUNK = (C < 32) ? C : 32;
    constexpr int NC = C / CHUNK;
    constexpr bool ACH = (C > 64);       // chunk+double-buffer A tile
    constexpr int JT = 64;
    constexpr int SA_FLOATS = ACH ? 2*32*132 : C*132;

    extern __shared__ float sm[];
    float* sA   = sm;                    // ACH ? [2][32][132] : [C][132]
    float* sB   = sA + SA_FLOATS;        // [2][CHUNK][68]
    float* sD   = sB + 2*CHUNK*68;       // [128][68] (reused as merge area)
    float* sSqB = sD + 128*68;           // [64]

    const int t  = threadIdx.x;
    const int tx = t & 15, ty = t >> 4;
    const int row = t & 127, half = t >> 7;
    const int b  = blockIdx.y;
    const int i0 = blockIdx.x * 128;
    const size_t baseRow = (size_t)b * NN;

    if (!ACH) {
        #pragma unroll
        for (int q = 0; q < (128*(C/4))/256; ++q) {
            int i = t & 127;
            int c4 = (t >> 7) + q*2;
            float4 v = *(const float4*)&H[(baseRow + i0 + i)*(size_t)C + c4*4];
            sA[(c4*4+0)*132 + i] = v.x;
            sA[(c4*4+1)*132 + i] = v.y;
            sA[(c4*4+2)*132 + i] = v.z;
            sA[(c4*4+3)*132 + i] = v.w;
        }
    }

    float td[16]; int ti[16];
    #pragma unroll
    for (int s = 0; s < 16; ++s) { td[s] = INFINITY; ti[s] = 0; }
    const float sqa = SQ[baseRow + i0 + row];

    for (int jt = 0; jt < NN/JT; ++jt) {
        __syncthreads();                 // prev scan done; buffers reusable
        const int j0 = jt*JT;
        if (t < JT) sSqB[t] = SQ[baseRow + j0 + t];

        // fill B chunk 0 into buffer 0
        #pragma unroll
        for (int q = 0; q < (JT*(CHUNK/4))/256; ++q) {
            int j = t & 63;
            int c4 = (t >> 6) + q*4;
            float4 v = *(const float4*)&H[(baseRow + j0 + j)*(size_t)C + c4*4];
            sB[(c4*4+0)*68 + j] = v.x;
            sB[(c4*4+1)*68 + j] = v.y;
            sB[(c4*4+2)*68 + j] = v.z;
            sB[(c4*4+3)*68 + j] = v.w;
        }
        // fill A chunk 0 (chunked path)
        if (ACH) {
            #pragma unroll
            for (int q = 0; q < 4; ++q) {
                int i = t & 127;
                int c4 = (t >> 7) + q*2;
                float4 v = *(const float4*)&H[(baseRow + i0 + i)*(size_t)C + c4*4];
                sA[(c4*4+0)*132 + i] = v.x;
                sA[(c4*4+1)*132 + i] = v.y;
                sA[(c4*4+2)*132 + i] = v.z;
                sA[(c4*4+3)*132 + i] = v.w;
            }
        }

        uint64_t acc2[4][4];             // rowpair rp (rows ty*8+2rp, +1), col rj
        #pragma unroll
        for (int a=0;a<4;a++)
            #pragma unroll
            for (int c=0;c<4;c++) acc2[a][c]=0ull;   // two packed +0.0f

        float4 preB[2];
        float4 preA[4];
        for (int ch = 0; ch < NC; ++ch) {
            __syncthreads();
            if (NC > 1 && ch + 1 < NC) {
                const int c0n = (ch+1)*CHUNK;
                #pragma unroll
                for (int q = 0; q < 2; ++q) {
                    int j = t & 63;
                    int c4 = (t >> 6) + q*4;
                    preB[q] = *(const float4*)&H[(baseRow + j0 + j)*(size_t)C + c0n + c4*4];
                }
                if (ACH) {
                    #pragma unroll
                    for (int q = 0; q < 4; ++q) {
                        int i = t & 127;
                        int c4 = (t >> 7) + q*2;
                        preA[q] = *(const float4*)&H[(baseRow + i0 + i)*(size_t)C + c0n + c4*4];
                    }
                }
            }
            const float* aBase = (ACH ? sA + (ch & 1)*(32*132)
                                      : sA + ch*CHUNK*132) + ty*8;
            const float* bBase = sB + (ch & 1)*(CHUNK*68) + tx*4;
            #pragma unroll
            for (int cc = 0; cc < CHUNK; ++cc) {
                ulonglong2 apA = *(const ulonglong2*)(aBase + cc*132);
                ulonglong2 apB = *(const ulonglong2*)(aBase + cc*132 + 4);
                float4 b0 = *(const float4*)(bBase + cc*68);
                uint64_t bd0 = pack2(b0.x, b0.x);
                uint64_t bd1 = pack2(b0.y, b0.y);
                uint64_t bd2 = pack2(b0.z, b0.z);
                uint64_t bd3 = pack2(b0.w, b0.w);
                uint64_t ap[4] = {apA.x, apA.y, apB.x, apB.y};
                #pragma unroll
                for (int rp=0;rp<4;rp++){
                    FMA_F32X2(acc2[rp][0], ap[rp], bd0);
                    FMA_F32X2(acc2[rp][1], ap[rp], bd1);
                    FMA_F32X2(acc2[rp][2], ap[rp], bd2);
                    FMA_F32X2(acc2[rp][3], ap[rp], bd3);
                }
            }
            if (NC > 1 && ch + 1 < NC) {
                float* dB = sB + ((ch+1) & 1)*(CHUNK*68);
                #pragma unroll
                for (int q = 0; q < 2; ++q) {
                    int j = t & 63;
                    int c4 = (t >> 6) + q*4;
                    dB[(c4*4+0)*68 + j] = preB[q].x;
                    dB[(c4*4+1)*68 + j] = preB[q].y;
                    dB[(c4*4+2)*68 + j] = preB[q].z;
                    dB[(c4*4+3)*68 + j] = preB[q].w;
                }
                if (ACH) {
                    float* dA = sA + ((ch+1) & 1)*(32*132);
                    #pragma unroll
                    for (int q = 0; q < 4; ++q) {
                        int i = t & 127;
                        int c4 = (t >> 7) + q*2;
                        dA[(c4*4+0)*132 + i] = preA[q].x;
                        dA[(c4*4+1)*132 + i] = preA[q].y;
                        dA[(c4*4+2)*132 + i] = preA[q].z;
                        dA[(c4*4+3)*132 + i] = preA[q].w;
                    }
                }
            }
        }
        // write dot tile: unpack rowpairs (lane0 = even row, lane1 = odd row)
        #pragma unroll
        for (int rp=0;rp<4;rp++){
            float lo0,hi0,lo1,hi1,lo2,hi2,lo3,hi3;
            unpack2(acc2[rp][0], lo0, hi0);
            unpack2(acc2[rp][1], lo1, hi1);
            unpack2(acc2[rp][2], lo2, hi2);
            unpack2(acc2[rp][3], lo3, hi3);
            *(float4*)(sD + (ty*8+rp*2  )*68 + tx*4) = make_float4(lo0,lo1,lo2,lo3);
            *(float4*)(sD + (ty*8+rp*2+1)*68 + tx*4) = make_float4(hi0,hi1,hi2,hi3);
        }
        __syncthreads();

        // scan: every thread processes its 32-candidate half of its row
        {
            const float* drow = sD + row*68 + half*32;
            const float* sqb  = sSqB + half*32;
            const int jb = j0 + half*32;
            #pragma unroll
            for (int g = 0; g < 8; ++g) {
                float4 v = *(const float4*)(drow + g*4);
                float dd[4] = {v.x, v.y, v.z, v.w};
                #pragma unroll
                for (int u = 0; u < 4; ++u) {
                    float d = sqa + sqb[g*4+u] - 2.f*dd[u];
                    if (d < td[15]) {
                        int jidx = jb + g*4 + u;
                        #pragma unroll
                        for (int s = 15; s >= 1; --s) {
                            bool cp = td[s-1] > d;
                            bool cs = td[s]   > d;
                            td[s] = cp ? td[s-1] : (cs ? d    : td[s]);
                            ti[s] = cp ? ti[s-1] : (cs ? jidx : ti[s]);
                        }
                        bool c0k = td[0] > d;
                        td[0] = c0k ? d    : td[0];
                        ti[0] = c0k ? jidx : ti[0];
                    }
                }
            }
        }
    }
    __syncthreads();
    // dump both halves' sorted lists into sD (reused as [128][64])
    {
        float* mrow = sD + row*64 + half*32;
        int*   mrowi = (int*)mrow + 16;
        #pragma unroll
        for (int s = 0; s < 16; ++s) { mrow[s] = td[s]; mrowi[s] = ti[s]; }
    }
    __syncthreads();
    // exact merge (lower distance wins; on equal distance, lower index wins)
    if (t < 128) {
        const float* dAl = sD + t*64;
        const int*   iAl = (const int*)dAl + 16;
        const float* dBl = dAl + 32;
        const int*   iBl = iAl + 32;
        int pa = 0, pb = 0;
        int* o = IDX + (baseRow + i0 + t)*KK;
        #pragma unroll
        for (int s = 0; s < 16; ++s) {
            float da = dAl[pa], db = dBl[pb];
            int   ia = iAl[pa], ib = iBl[pb];
            bool takeA = (da < db) || (da == db && ia < ib);
            o[s] = takeA ? ia : ib;
            pa += takeA ? 1 : 0;
            pb += takeA ? 0 : 1;
        }
    }
}

// ---------------- cov features: [x, cov(knn xyz).flatten(9)] -> 12 ch ----------------
__global__ void k_cov(const float* __restrict__ X, const int* __restrict__ IDX,
                      float* __restrict__ OUT){
    int p = blockIdx.x*blockDim.x + threadIdx.x;
    if (p >= NPTS) return;
    int b = p >> 11;
    const int* id = IDX + (size_t)p*KK;
    float px[16], py[16], pz[16];
    float mx=0.f,my=0.f,mz=0.f;
    #pragma unroll
    for (int k=0;k<16;k++){
        int j = id[k];
        const float* q = X + ((size_t)(b<<11) + j)*3;
        px[k]=q[0]; py[k]=q[1]; pz[k]=q[2];
        mx+=px[k]; my+=py[k]; mz+=pz[k];
    }
    mx *= (1.f/16.f); my *= (1.f/16.f); mz *= (1.f/16.f);
    float c00=0,c01=0,c02=0,c11=0,c12=0,c22=0;
    #pragma unroll
    for (int k=0;k<16;k++){
        float cx=px[k]-mx, cy=py[k]-my, cz=pz[k]-mz;
        c00=fmaf(cx,cx,c00); c01=fmaf(cx,cy,c01); c02=fmaf(cx,cz,c02);
        c11=fmaf(cy,cy,c11); c12=fmaf(cy,cz,c12); c22=fmaf(cz,cz,c22);
    }
    const float* xi = X + (size_t)p*3;
    float* o = OUT + (size_t)p*12;
    o[0]=xi[0]; o[1]=xi[1]; o[2]=xi[2];
    o[3]=c00; o[4]=c01; o[5]=c02;
    o[6]=c01; o[7]=c11; o[8]=c12;
    o[9]=c02; o[10]=c12; o[11]=c22;
}

// ---------------- pointwise dense (kernel_size=1 conv), optional BN+ReLU ----------------
template<int CIN,int COUT,int RELU,int BN>
__global__ __launch_bounds__(256) void k_dense(const float* __restrict__ X,
        const float* __restrict__ W, const float* __restrict__ bias,
        const float* __restrict__ bg, const float* __restrict__ bb,
        const float* __restrict__ bm, const float* __restrict__ bv,
        float* __restrict__ OUT){
    extern __shared__ float sm[];
    float* Xs = sm;                  // [64][CIN] (CIN % 4 == 0)
    float* Ws = Xs + 64*CIN;         // [CIN][COUT]
    const int t = threadIdx.x;
    const size_t row0 = (size_t)blockIdx.x * 64;
    for (int e = t; e < (64*CIN)/4; e += 256)
        *(float4*)&Xs[e*4] = *(const float4*)&X[row0*CIN + e*4];
    for (int e = t; e < (CIN*COUT)/4; e += 256)
        *(float4*)&Ws[e*4] = *(const float4*)&W[e*4];
    __syncthreads();
    constexpr int CQ = COUT/4;
    for (int q = t; q < 32*CQ; q += 256) {
        int rp = q / CQ;
        int c4 = (q - rp*CQ)*4;
        float4 b4 = *(const float4*)(bias + c4);
        float a0[4] = {b4.x,b4.y,b4.z,b4.w};
        float a1[4] = {b4.x,b4.y,b4.z,b4.w};
        #pragma unroll 8
        for (int k=0;k<CIN;k++){
            float x0 = Xs[rp*CIN+k];
            float x1 = Xs[(rp+32)*CIN+k];
            float4 w = *(const float4*)(Ws + k*COUT + c4);
            a0[0]=fmaf(x0,w.x,a0[0]); a0[1]=fmaf(x0,w.y,a0[1]);
            a0[2]=fmaf(x0,w.z,a0[2]); a0[3]=fmaf(x0,w.w,a0[3]);
            a1[0]=fmaf(x1,w.x,a1[0]); a1[1]=fmaf(x1,w.y,a1[1]);
            a1[2]=fmaf(x1,w.z,a1[2]); a1[3]=fmaf(x1,w.w,a1[3]);
        }
        #pragma unroll
        for (int u=0;u<4;u++){
            float v0=a0[u], v1=a1[u];
            if (BN){
                int c = c4+u;
                float s   = bg[c]*rsqrtf(bv[c]+1e-3f);
                float off = bb[c] - bm[c]*s;
                v0 = fmaf(v0,s,off); v1 = fmaf(v1,s,off);
            }
            if (RELU){ v0=fmaxf(v0,0.f); v1=fmaxf(v1,0.f); }
            a0[u]=v0; a1[u]=v1;
        }
        *(float4*)(OUT + (row0+rp)*COUT + c4)    = make_float4(a0[0],a0[1],a0[2],a0[3]);
        *(float4*)(OUT + (row0+rp+32)*COUT + c4) = make_float4(a1[0],a1[1],a1[2],a1[3]);
    }
}

// ---------------- dense 128->128 (g2_lin): k-chunked, 3 CTAs/SM ----------------
__global__ __launch_bounds__(256,3) void k_dense128(const float* __restrict__ X,
        const float* __restrict__ W, const float* __restrict__ bias,
        float* __restrict__ OUT){
    extern __shared__ float sm[];
    float* Xs = sm;            // [64][128]
    float* Ws = Xs + 64*128;   // [2][32][128]
    const int t = threadIdx.x;
    const int c4 = (t & 31)*4;
    const int rp0 = t >> 5;    // 0..7
    const size_t row0 = (size_t)blockIdx.x * 64;

    #pragma unroll
    for (int q = 0; q < 8; ++q) {
        int e = t + q*256;
        *(float4*)&Xs[e*4] = *(const float4*)&X[row0*128 + e*4];
    }
    #pragma unroll
    for (int q = 0; q < 4; ++q) {
        int e = t + q*256;
        int k = e >> 5, cc4 = e & 31;
        *(float4*)&Ws[k*128 + cc4*4] = *(const float4*)&W[(size_t)k*128 + cc4*4];
    }

    float acc[8][4];
    {
        float4 b4 = *(const float4*)(bias + c4);
        #pragma unroll
        for (int m=0;m<8;m++){ acc[m][0]=b4.x; acc[m][1]=b4.y; acc[m][2]=b4.z; acc[m][3]=b4.w; }
    }

    float4 preW[4];
    for (int kc = 0; kc < 4; ++kc) {
        __syncthreads();
        if (kc + 1 < 4) {
            const int k0n = (kc+1)*32;
            #pragma unroll
            for (int q = 0; q < 4; ++q) {
                int e = t + q*256;
                int k = e >> 5, cc4 = e & 31;
                preW[q] = *(const float4*)&W[(size_t)(k0n + k)*128 + cc4*4];
            }
        }
        const float* wb = Ws + (kc & 1)*(32*128);
        #pragma unroll
        for (int kk = 0; kk < 32; ++kk) {
            float4 w = *(const float4*)(wb + kk*128 + c4);
            int k = kc*32 + kk;
            #pragma unroll
            for (int m = 0; m < 8; ++m) {
                int r = rp0 + ((m & 3) << 3) + ((m >> 2) << 5);
                float x = Xs[r*128 + k];
                acc[m][0]=fmaf(x,w.x,acc[m][0]); acc[m][1]=fmaf(x,w.y,acc[m][1]);
                acc[m][2]=fmaf(x,w.z,acc[m][2]); acc[m][3]=fmaf(x,w.w,acc[m][3]);
            }
        }
        if (kc + 1 < 4) {
            float* wdst = Ws + ((kc+1) & 1)*(32*128);
            #pragma unroll
            for (int q = 0; q < 4; ++q) {
                int e = t + q*256;
                int k = e >> 5, cc4 = e & 31;
                *(float4*)&wdst[k*128 + cc4*4] = preW[q];
            }
        }
    }
    #pragma unroll
    for (int m = 0; m < 8; ++m) {
        int r = rp0 + ((m & 3) << 3) + ((m >> 2) << 5);
        *(float4*)(OUT + (row0 + r)*128 + c4) =
            make_float4(acc[m][0],acc[m][1],acc[m][2],acc[m][3]);
    }
}

// ---------------- gather neighbors + max over k ----------------
template<int C>
__global__ void k_gmax(const float* __restrict__ H, const int* __restrict__ IDX,
                       float* __restrict__ OUT){
    constexpr int CQ = C/4;
    int e = blockIdx.x*blockDim.x + threadIdx.x;
    if (e >= NPTS*CQ) return;
    int p = e / CQ, c4 = (e - p*CQ)*4;
    int b = p >> 11;
    const int* id = IDX + (size_t)p*KK;
    float4 m = make_float4(-INFINITY,-INFINITY,-INFINITY,-INFINITY);
    #pragma unroll
    for (int k=0;k<16;k++){
        int j = id[k];
        float4 v = *(const float4*)(H + ((size_t)(b<<11)+j)*C + c4);
        m.x=fmaxf(m.x,v.x); m.y=fmaxf(m.y,v.y);
        m.z=fmaxf(m.z,v.z); m.w=fmaxf(m.w,v.w);
    }
    *(float4*)(OUT + (size_t)p*C + c4) = m;
}

// ---------------- 128->1024 GEMM fused with bias + global max over N ----------------
// f32x2 rowpair mainloop (lane0 = even row, lane1 = odd row); bit-identical.
__global__ __launch_bounds__(256,2) void k_gemm_pool(const float* __restrict__ X,
        const float* __restrict__ W, const float* __restrict__ bias,
        float* __restrict__ pool){
    extern __shared__ float sm[];
    float* XsT  = sm;              // [128 k][132 i]
    float* Ws   = XsT + 128*132;   // [128 k][68 c]
    float* sred = Ws  + 128*68;    // [64 c][17]
    const int t = threadIdx.x, tx = t & 15, ty = t >> 4;
    const int b = blockIdx.z;
    const size_t row0 = (size_t)b*NN + (size_t)blockIdx.y*128;
    const int c0 = blockIdx.x*64;

    #pragma unroll
    for (int q = 0; q < 16; ++q) {
        int i = t & 127;
        int k4 = (t >> 7) + q*2;
        float4 v = *(const float4*)&X[(row0 + i)*128 + k4*4];
        XsT[(k4*4+0)*132 + i] = v.x;
        XsT[(k4*4+1)*132 + i] = v.y;
        XsT[(k4*4+2)*132 + i] = v.z;
        XsT[(k4*4+3)*132 + i] = v.w;
    }
    #pragma unroll
    for (int q = 0; q < 8; ++q) {
        int c4 = t & 15;
        int k = (t >> 4) + q*16;
        *(float4*)&Ws[k*68 + c4*4] = *(const float4*)&W[(size_t)k*1024 + c0 + c4*4];
    }
    __syncthreads();

    uint64_t acc2[4][4];
    #pragma unroll
    for (int a=0;a<4;a++)
        #pragma unroll
        for (int c=0;c<4;c++) acc2[a][c]=0ull;

    const float* aBase = XsT + ty*8;
    const float* wBase = Ws  + tx*4;
    #pragma unroll 8
    for (int k=0;k<128;k++){
        ulonglong2 apA = *(const ulonglong2*)(aBase + k*132);
        ulonglong2 apB = *(const ulonglong2*)(aBase + k*132 + 4);
        float4 w0 = *(const float4*)(wBase + k*68);
        uint64_t wd0 = pack2(w0.x, w0.x);
        uint64_t wd1 = pack2(w0.y, w0.y);
        uint64_t wd2 = pack2(w0.z, w0.z);
        uint64_t wd3 = pack2(w0.w, w0.w);
        uint64_t ap[4] = {apA.x, apA.y, apB.x, apB.y};
        #pragma unroll
        for (int rp=0;rp<4;rp++){
            FMA_F32X2(acc2[rp][0], ap[rp], wd0);
            FMA_F32X2(acc2[rp][1], ap[rp], wd1);
            FMA_F32X2(acc2[rp][2], ap[rp], wd2);
            FMA_F32X2(acc2[rp][3], ap[rp], wd3);
        }
    }
    // rows = ty*8 + 2rp + lane; per-col max over this thread's 8 rows (order 0..7)
    #pragma unroll
    for (int rj=0;rj<4;rj++){
        float m = -INFINITY;
        #pragma unroll
        for (int rp=0;rp<4;rp++){
            float lo, hi;
            unpack2(acc2[rp][rj], lo, hi);
            m = fmaxf(m, lo);
            m = fmaxf(m, hi);
        }
        sred[(tx*4+rj)*17 + ty] = m;
    }
    __syncthreads();
    if (t < 64){
        float m = sred[t*17];
        #pragma unroll
        for (int q=1;q<16;q++) m = fmaxf(m, sred[t*17+q]);
        m += bias[c0 + t];
        atomicMaxF(&pool[b*1024 + c0 + t], m);
    }
}

__global__ void k_init(float* __restrict__ p, int n){
    int e = blockIdx.x*blockDim.x + threadIdx.x;
    if (e < n) p[e] = -INFINITY;
}

// ---------------- tiny FC layers over pooled [B, CIN] ----------------
template<int CIN,int COUT,int RELU>
__global__ __launch_bounds__(256) void k_fc(const float* __restrict__ IN,
        const float* __restrict__ W, const float* __restrict__ bias,
        float* __restrict__ OUT){
    __shared__ float Ps[CIN];
    const int t = threadIdx.x;
    const int b = blockIdx.y;
    const int c = blockIdx.x*256 + t;
    for (int e=t;e<CIN;e+=256) Ps[e]=IN[b*CIN+e];
    __syncthreads();
    float acc = bias[c];
    #pragma unroll 8
    for (int k=0;k<CIN;k++) acc = fmaf(Ps[k], W[(size_t)k*COUT + c], acc);
    if (RELU) acc = fmaxf(acc, 0.f);
    OUT[b*COUT + c] = acc;
}

// ---------------- host ----------------
static inline int knn_smem(int C){
    int ch = C < 32 ? C : 32;
    int sa = (C > 64) ? 2*32*132 : C*132;
    return (sa + 2*ch*68 + 128*68 + 64)*4;
}
static inline int dense_smem(int cin, int cout){
    return (64*cin + cin*cout)*4;
}
#define GEMM_SMEM ((128*132 + 128*68 + 64*17)*4)
#define DENSE128_SMEM ((64*128 + 2*32*128)*4)

extern "C" void kernel_launch(void* const* d_in, const int* in_sizes, int n_in,
                              void* d_out, int out_size){
    const float* x    = (const float*)d_in[0];
    const float* c1w  = (const float*)d_in[1];
    const float* c1b  = (const float*)d_in[2];
    const float* c2w  = (const float*)d_in[3];
    const float* c2b  = (const float*)d_in[4];
    const float* c3w  = (const float*)d_in[5];
    const float* c3b  = (const float*)d_in[6];
    const float* g1lw = (const float*)d_in[7];
    const float* g1lb = (const float*)d_in[8];
    const float* g1cw = (const float*)d_in[9];
    const float* g1cb = (const float*)d_in[10];
    const float* g2lw = (const float*)d_in[11];
    const float* g2lb = (const float*)d_in[12];
    const float* g2cw = (const float*)d_in[13];
    const float* g2cb = (const float*)d_in[14];
    const float* c4w  = (const float*)d_in[15];
    const float* c4b  = (const float*)d_in[16];
    const float* c5w  = (const float*)d_in[17];
    const float* c5b  = (const float*)d_in[18];
    const float* bn1g = (const float*)d_in[19];
    const float* bn1b = (const float*)d_in[20];
    const float* bn1m = (const float*)d_in[21];
    const float* bn1v = (const float*)d_in[22];
    const float* bn2g = (const float*)d_in[23];
    const float* bn2b = (const float*)d_in[24];
    const float* bn2m = (const float*)d_in[25];
    const float* bn2v = (const float*)d_in[26];
    const float* bn3g = (const float*)d_in[27];
    const float* bn3b = (const float*)d_in[28];
    const float* bn3m = (const float*)d_in[29];
    const float* bn3v = (const float*)d_in[30];
    float* out = (float*)d_out;

    float *A,*B,*SQ,*POOL,*Y; int* ID;
    cudaGetSymbolAddress((void**)&A, gA);
    cudaGetSymbolAddress((void**)&B, gB);
    cudaGetSymbolAddress((void**)&SQ, gSq);
    cudaGetSymbolAddress((void**)&POOL, gPool);
    cudaGetSymbolAddress((void**)&Y, gY);
    cudaGetSymbolAddress((void**)&ID, gIdx);

    cudaFuncSetAttribute(k_knn<64>,  cudaFuncAttributeMaxDynamicSharedMemorySize, knn_smem(64));
    cudaFuncSetAttribute(k_knn<128>, cudaFuncAttributeMaxDynamicSharedMemorySize, knn_smem(128));
    cudaFuncSetAttribute(k_gemm_pool, cudaFuncAttributeMaxDynamicSharedMemorySize, GEMM_SMEM);
    cudaFuncSetAttribute(k_dense128,  cudaFuncAttributeMaxDynamicSharedMemorySize, DENSE128_SMEM);
    cudaFuncSetAttribute((void*)k_dense<64,128,1,0>, cudaFuncAttributeMaxDynamicSharedMemorySize,
                         dense_smem(64,128));

    const dim3 knnGrid(NN/128, BB);   // 256 blocks

    // stage 0: knn on xyz (specialized, batch-resident) + covariance features
    k_sq<<<(NPTS*32)/256, 256>>>(x, SQ, 3);
    k_knn3<<<knnGrid, 256>>>(x, SQ, ID);
    k_cov<<<NPTS/256, 256>>>(x, ID, A);                       // A: [*,12]

    // MLP stack with BN+ReLU
    k_dense<12,12,1,1><<<NPTS/64, 256, dense_smem(12,12)>>>(A, c1w, c1b, bn1g,bn1b,bn1m,bn1v, B);
    k_dense<12,64,1,1><<<NPTS/64, 256, dense_smem(12,64)>>>(B, c2w, c2b, bn2g,bn2b,bn2m,bn2v, A);
    k_dense<64,64,1,1><<<NPTS/64, 256, dense_smem(64,64)>>>(A, c3w, c3b, bn3g,bn3b,bn3m,bn3v, B); // h64 in B

    // graph layer 1 (C=64 -> 128, relu)
    k_sq<<<(NPTS*32)/256, 256>>>(B, SQ, 64);
    k_knn<64><<<knnGrid, 256, knn_smem(64)>>>(B, SQ, ID);
    k_gmax<64><<<(NPTS*16)/256, 256>>>(B, ID, A);
    k_dense<64,64,0,0><<<NPTS/64, 256, dense_smem(64,64)>>>(A, g1lw, g1lb, 0,0,0,0, B);
    k_dense<64,128,1,0><<<NPTS/64, 256, dense_smem(64,128)>>>(B, g1cw, g1cb, 0,0,0,0, A); // h128 in A

    // graph layer 2 (C=128 -> 1024, no relu) fused with global max pool
    k_sq<<<(NPTS*32)/256, 256>>>(A, SQ, 128);
    k_knn<128><<<knnGrid, 256, knn_smem(128)>>>(A, SQ, ID);
    k_gmax<128><<<(NPTS*32)/256, 256>>>(A, ID, B);
    k_dense128<<<NPTS/64, 256, DENSE128_SMEM>>>(B, g2lw, g2lb, A);
    k_init<<<(BB*1024)/256, 256>>>(POOL, BB*1024);
    k_gemm_pool<<<dim3(1024/64, NN/128, BB), 256, GEMM_SMEM>>>(A, g2cw, g2cb, POOL);

    // head
    k_fc<1024,1024,1><<<dim3(1024/256, BB), 256>>>(POOL, c4w, c4b, Y);
    k_fc<1024,512,0><<<dim3(512/256, BB), 256>>>(Y, c5w, c5b, out);
}